// round 16
// baseline (speedup 1.0000x reference)
#include <cuda_runtime.h>
#include <cuda_fp16.h>

// Gaussian-splat render, round 12: tensor-core quadratic + hybrid exp.
//   out[n,c] = sum_m exp(-0.5 * d^T C_m^-1 d) * cols[m,c]
//
// R11 confirmed the MUFU floor (ex2 = 4 values/cyc/SMSP; occ-invariant).
// R12: (1) quadratic eval moved to HMMA: T = F @ Cq with hi/lo split
// features/coeffs (K=16) and c0 added via f32 accumulator init; the quad
// D-fragment maps exactly onto the color-mma A-fragment (1 cvt/pair).
// (2) 3/8 of chunks compute exp2 on the FMA pipe (n/f split + packed-scale
// IMAD + deg-3 poly, k/4-scaled coeffs, w=v^4), rest on MUFU -> both pipes
// ~balanced at ~10 cyc/pair vs 16 before.
// (3) pixel features precomputed in mma-fragment layout (2MB table,
// 4x LDG.128 per warp-round, L1-shared across the CTA's 16 warps).

typedef unsigned long long u64;

static constexpr int N_GAUSS = 2048;
static constexpr int N_CHUNK = 128;     // 16 Gaussians per chunk
static constexpr int N_GROUP = 1024;    // 64 pixels per group
static constexpr int BLK     = 512;     // 16 warps = 16 slices
static constexpr int GRID    = 148;
static constexpr int ROUNDS  = 7;

// smem table (u32 units): Bq frags | color frags | c0 f32
static constexpr int BQ_U32  = N_CHUNK * 32 * 4;   // 16384 (64KB)
static constexpr int CF_U32  = N_CHUNK * 32 * 2;   // 8192  (32KB)
static constexpr int C0_U32  = N_CHUNK * 16;       // 2048  (8KB)
static constexpr int TAB_U32 = BQ_U32 + CF_U32 + C0_U32;   // 26624
static constexpr int RED_F32 = 16 * 192;           // 3072
static constexpr size_t SMEM_BYTES = (size_t)(TAB_U32 + RED_F32) * 4; // 118784

__device__ unsigned g_tab3[TAB_U32];
__device__ uint4    g_ft[N_GROUP * 4 * 32];        // feature fragments, 2MB

__device__ __forceinline__ unsigned h2u(__half2 h) {
    return *reinterpret_cast<unsigned*>(&h);
}
__device__ __forceinline__ __half2 u2h(unsigned u) {
    return *reinterpret_cast<__half2*>(&u);
}
__device__ __forceinline__ unsigned ex2_h2(unsigned v) {
    unsigned r; asm("ex2.approx.f16x2 %0, %1;" : "=r"(r) : "r"(v)); return r;
}
__device__ __forceinline__ unsigned cvtpack(float hi, float lo) {
    unsigned r;
    asm("cvt.rn.f16x2.f32 %0, %1, %2;" : "=r"(r) : "f"(hi), "f"(lo));
    return r;
}
__device__ __forceinline__ void mma16816(float& d0, float& d1, float& d2, float& d3,
                                         unsigned a0, unsigned a1, unsigned a2, unsigned a3,
                                         unsigned b0, unsigned b1)
{
    asm("mma.sync.aligned.m16n8k16.row.col.f32.f16.f16.f32 "
        "{%0,%1,%2,%3}, {%4,%5,%6,%7}, {%8,%9}, {%0,%1,%2,%3};"
        : "+f"(d0), "+f"(d1), "+f"(d2), "+f"(d3)
        : "r"(a0), "r"(a1), "r"(a2), "r"(a3), "r"(b0), "r"(b1));
}

// FMA-pipe exp2(-4*tq) for tq >= 0 (coeffs pre-scaled by k/4): w = (2^-tq)^4
__device__ __forceinline__ unsigned polyexp(unsigned tu) {
    __half2 t = u2h(tu);
    t = __hmin2(t, __floats2half2_rn(15.0f, 15.0f));
    __half2 u = __hadd2(t, __floats2half2_rn(1024.0f, 1024.0f));   // n=round(t) in mantissa
    __half2 n = __hadd2(u, __floats2half2_rn(-1024.0f, -1024.0f)); // n as fp16 (exact)
    __half2 f = __hsub2(t, n);                                     // f in [-0.5, 0.5]
    unsigned nb = h2u(u) & 0x001F001Fu;
    unsigned sm = 0x3C003C00u - nb * 1024u;                        // 2^-n per half
    __half2 p = __hfma2(f, __floats2half2_rn(-0.0559208f, -0.0559208f),
                        __floats2half2_rn(0.2426310f, 0.2426310f));
    p = __hfma2(p, f, __floats2half2_rn(-0.6931212f, -0.6931212f));
    p = __hfma2(p, f, __floats2half2_rn(0.9999249f, 0.9999249f));  // ~2^-f
    __half2 v = __hmul2(p, u2h(sm));                               // 2^-t
    v = __hmul2(v, v);
    v = __hmul2(v, v);                                             // w = 2^-4t
    return h2u(v);
}

// ---- Prep 1: per-Gaussian Bq fragments (hi/lo), color fragments, c0 ----
__global__ void prep1_kernel(const float* __restrict__ mus,
                             const float* __restrict__ covs,
                             const float* __restrict__ cols)
{
    int idx = blockIdx.x * blockDim.x + threadIdx.x;
    if (idx >= N_CHUNK * 32) return;
    int chunk = idx >> 5, lane = idx & 31;
    bool poly = (chunk & 7) < 3;
    const float kk = 0.72134752044448170368f;   // 0.5 * log2(e)
    float s = poly ? kk * 0.25f : -kk;
    int col = lane >> 2, kb = (lane & 3) * 2;

    unsigned frag[4];
    #pragma unroll
    for (int nh = 0; nh < 2; ++nh) {
        int m = chunk * 16 + nh * 8 + col;
        float2 mu = ((const float2*)mus)[m];
        float4 cv = ((const float4*)covs)[m];
        float a = cv.x, b = cv.y, c = cv.w;
        float idet = 1.0f / (a * c - b * b);
        float p00 = c * idet, p01 = -b * idet, p11 = a * idet;
        float C[5];
        C[0] = s * (-2.0f * (p00 * mu.x + p01 * mu.y));  // x
        C[1] = s * (-2.0f * (p01 * mu.x + p11 * mu.y));  // y
        C[2] = s * p00;                                  // x^2
        C[3] = s * (2.0f * p01);                         // x*y
        C[4] = s * p11;                                  // y^2
        __half sv[16];
        #pragma unroll
        for (int i = 0; i < 5; ++i) {
            __half hi = __float2half_rn(C[i]);
            __half lo = __float2half_rn(C[i] - __half2float(hi));
            sv[i] = hi; sv[5 + i] = hi; sv[10 + i] = lo;
        }
        sv[15] = __float2half_rn(0.0f);
        frag[nh * 2 + 0] = h2u(__halves2half2(sv[kb],     sv[kb + 1]));
        frag[nh * 2 + 1] = h2u(__halves2half2(sv[kb + 8], sv[kb + 9]));
    }
    ((uint4*)g_tab3)[chunk * 32 + lane] =
        make_uint4(frag[0], frag[1], frag[2], frag[3]);

    // c0 (f32, used as mma accumulator init)
    if (lane < 16) {
        int m = chunk * 16 + lane;
        float2 mu = ((const float2*)mus)[m];
        float4 cv = ((const float4*)covs)[m];
        float a = cv.x, b = cv.y, c = cv.w;
        float idet = 1.0f / (a * c - b * b);
        float p00 = c * idet, p01 = -b * idet, p11 = a * idet;
        float C0 = s * (p00 * mu.x * mu.x + 2.0f * p01 * mu.x * mu.y
                        + p11 * mu.y * mu.y);
        ((float*)(g_tab3 + BQ_U32 + CF_U32))[chunk * 16 + lane] = C0;
    }

    // color B-fragments (validated layout from R9/R10)
    {
        int t = lane;
        int cc = t >> 2;
        int p0 = t & 3, p1 = (t & 3) + 4;
        int gA0 = chunk * 16 + 2 * p0, gA1 = gA0 + 1;
        int gB0 = chunk * 16 + 2 * p1, gB1 = gB0 + 1;
        float b00 = (cc < 3) ? cols[gA0 * 3 + cc] : 0.f;
        float b01 = (cc < 3) ? cols[gA1 * 3 + cc] : 0.f;
        float b10 = (cc < 3) ? cols[gB0 * 3 + cc] : 0.f;
        float b11 = (cc < 3) ? cols[gB1 * 3 + cc] : 0.f;
        g_tab3[BQ_U32 + chunk * 64 + t * 2 + 0] = h2u(__floats2half2_rn(b00, b01));
        g_tab3[BQ_U32 + chunk * 64 + t * 2 + 1] = h2u(__floats2half2_rn(b10, b11));
    }
}

// ---- Prep 2: pixel feature fragments (hi/lo), mma-A layout ----
__global__ void prep2_kernel(const float* __restrict__ x)
{
    int idx = blockIdx.x * blockDim.x + threadIdx.x;
    if (idx >= N_GROUP * 4 * 32) return;
    int lane = idx & 31, mt = (idx >> 5) & 3, g = idx >> 7;
    int qr = lane >> 2, qc = lane & 3;

    unsigned o[4];
    #pragma unroll
    for (int h = 0; h < 2; ++h) {
        int pix = g * 64 + mt * 16 + qr + h * 8;
        float px = x[2 * pix], py = x[2 * pix + 1];
        float fv[5] = { px, py, px * px, px * py, py * py };
        __half hs[16];
        #pragma unroll
        for (int i = 0; i < 5; ++i) {
            __half hi = __float2half_rn(fv[i]);
            __half lo = __float2half_rn(fv[i] - __half2float(hi));
            hs[i] = hi; hs[5 + i] = lo; hs[10 + i] = hi;
        }
        hs[15] = __float2half_rn(0.0f);
        o[h]     = h2u(__halves2half2(hs[2 * qc],     hs[2 * qc + 1]));
        o[h + 2] = h2u(__halves2half2(hs[2 * qc + 8], hs[2 * qc + 9]));
    }
    g_ft[idx] = make_uint4(o[0], o[1], o[2], o[3]);
}

// ---- Main render ----
__global__ __launch_bounds__(BLK, 1)
void render_kernel(const float* __restrict__ x, float* __restrict__ out)
{
    extern __shared__ unsigned sh[];
    const int tid = threadIdx.x;
    const int wid = tid >> 5;              // warp = Gaussian slice (0..15)
    const int lane = tid & 31;
    const int qr = lane >> 2;
    const int qc = lane & 3;

    // bulk copy tables into shared
    {
        const uint4* src = (const uint4*)g_tab3;
        uint4* dst = (uint4*)sh;
        for (int i = tid; i < TAB_U32 / 4; i += BLK) dst[i] = src[i];
    }
    const unsigned* shbq = sh;
    const unsigned* shcf = sh + BQ_U32;
    const float*    shc0 = (const float*)(sh + BQ_U32 + CF_U32);
    float* red = (float*)(sh + TAB_U32);   // [16 slices][192]
    __syncthreads();

    for (int rnd = 0; rnd < ROUNDS; ++rnd) {
        const int group = blockIdx.x + GRID * rnd;
        const bool act = (group < N_GROUP);

        if (act) {
            uint4 af[4];
            #pragma unroll
            for (int mt = 0; mt < 4; ++mt)
                af[mt] = g_ft[(group * 4 + mt) * 32 + lane];

            float colD[4][4];
            #pragma unroll
            for (int mt = 0; mt < 4; ++mt)
                colD[mt][0] = colD[mt][1] = colD[mt][2] = colD[mt][3] = 0.f;

            #pragma unroll
            for (int j = 0; j < 8; ++j) {
                const int chunk = wid * 8 + j;
                uint4 bq = *(const uint4*)(shbq + (chunk * 32 + lane) * 4);
                u64 bb = *(const u64*)(shcf + chunk * 64 + lane * 2);
                unsigned cb0 = (unsigned)bb, cb1 = (unsigned)(bb >> 32);
                float2 c0a = *(const float2*)(shc0 + chunk * 16 + qc * 2);
                float2 c0b = *(const float2*)(shc0 + chunk * 16 + 8 + qc * 2);

                #pragma unroll
                for (int mt = 0; mt < 4; ++mt) {
                    float d0 = c0a.x, d1 = c0a.y, d2 = c0a.x, d3 = c0a.y;
                    mma16816(d0, d1, d2, d3,
                             af[mt].x, af[mt].y, af[mt].z, af[mt].w,
                             bq.x, bq.y);
                    float e0 = c0b.x, e1 = c0b.y, e2 = c0b.x, e3 = c0b.y;
                    mma16816(e0, e1, e2, e3,
                             af[mt].x, af[mt].y, af[mt].z, af[mt].w,
                             bq.z, bq.w);

                    unsigned a0 = cvtpack(d1, d0);
                    unsigned a1 = cvtpack(d3, d2);
                    unsigned a2 = cvtpack(e1, e0);
                    unsigned a3 = cvtpack(e3, e2);

                    if (j < 3) {        // poly chunks (+k/4 scale)
                        a0 = polyexp(a0); a1 = polyexp(a1);
                        a2 = polyexp(a2); a3 = polyexp(a3);
                    } else {            // MUFU chunks (-k scale)
                        a0 = ex2_h2(a0); a1 = ex2_h2(a1);
                        a2 = ex2_h2(a2); a3 = ex2_h2(a3);
                    }

                    mma16816(colD[mt][0], colD[mt][1], colD[mt][2], colD[mt][3],
                             a0, a1, a2, a3, cb0, cb1);
                }
            }

            // write this slice's partial rgb: red[slice][pix_in_grp*3 + c]
            float* rp = red + wid * 192;
            if (qc == 0) {          // cols 0,1 = R,G
                #pragma unroll
                for (int mt = 0; mt < 4; ++mt) {
                    int p0 = mt * 16 + qr, p1 = p0 + 8;
                    rp[p0 * 3 + 0] = colD[mt][0];
                    rp[p0 * 3 + 1] = colD[mt][1];
                    rp[p1 * 3 + 0] = colD[mt][2];
                    rp[p1 * 3 + 1] = colD[mt][3];
                }
            } else if (qc == 1) {   // col 2 = B
                #pragma unroll
                for (int mt = 0; mt < 4; ++mt) {
                    int p0 = mt * 16 + qr, p1 = p0 + 8;
                    rp[p0 * 3 + 2] = colD[mt][0];
                    rp[p1 * 3 + 2] = colD[mt][2];
                }
            }
        }
        __syncthreads();

        if (act && tid < 192) {
            float s = 0.f;
            #pragma unroll
            for (int w = 0; w < 16; ++w) s += red[w * 192 + tid];
            out[group * 192 + tid] = s;
        }
        __syncthreads();
    }
}

extern "C" void kernel_launch(void* const* d_in, const int* in_sizes, int n_in,
                              void* d_out, int out_size)
{
    const float* x    = (const float*)d_in[0];
    const float* mus  = (const float*)d_in[1];
    const float* covs = (const float*)d_in[2];
    const float* cols = (const float*)d_in[3];
    float* out = (float*)d_out;

    prep1_kernel<<<(N_CHUNK * 32 + 255) / 256, 256>>>(mus, covs, cols);
    prep2_kernel<<<(N_GROUP * 4 * 32 + 255) / 256, 256>>>(x);

    cudaFuncSetAttribute(render_kernel,
                         cudaFuncAttributeMaxDynamicSharedMemorySize,
                         (int)SMEM_BYTES);
    render_kernel<<<GRID, BLK, SMEM_BYTES>>>(x, out);
}